// round 15
// baseline (speedup 1.0000x reference)
#include <cuda_runtime.h>
#include <cuda_fp16.h>
#include <math.h>
#include <cstdint>

// ---------------------------------------------------------------------------
// B=2048, D=512, ATT=128, HID=256, MAX_ATOMS=50. N = 52176 at runtime.
// Single-pass fp16 HMMA. GEMM: 128x128 CTA, 256 thr, 2 CTAs/SM.
// K processed in 64-wide SUPER-chunks: one 20480B cp.async.bulk per operand
// + one mbarrier per super-chunk; one __syncthreads per super-chunk.
// ---------------------------------------------------------------------------
#define MAXB     2048
#define NPB_MAX  56320          // >= N + B rows
#define ATT      128
#define HID      256
#define MAXA     50
#define MT_MAX   440            // max 128-row tiles
#define CHUNK_B  10240          // one 32-K chunk image: 128 rows x 80 B

// ---------------------------------------------------------------------------
// PTX helpers (<= sm_90 non-'a' features only)
// ---------------------------------------------------------------------------
__device__ __forceinline__ uint32_t smem_u32(const void* p) {
    uint32_t a;
    asm("{ .reg .u64 t; cvta.to.shared.u64 t, %1; cvt.u32.u64 %0, t; }" : "=r"(a) : "l"(p));
    return a;
}

#define LDSM4(r, addr) \
    asm volatile("ldmatrix.sync.aligned.m8n8.x4.shared.b16 {%0,%1,%2,%3}, [%4];" \
        : "=r"((r)[0]), "=r"((r)[1]), "=r"((r)[2]), "=r"((r)[3]) : "r"(addr))

#define MMA16816(d, a, bp) \
    asm volatile("mma.sync.aligned.m16n8k16.row.col.f32.f16.f16.f32 " \
        "{%0,%1,%2,%3}, {%4,%5,%6,%7}, {%8,%9}, {%0,%1,%2,%3};" \
        : "+f"((d)[0]), "+f"((d)[1]), "+f"((d)[2]), "+f"((d)[3]) \
        : "r"((a)[0]), "r"((a)[1]), "r"((a)[2]), "r"((a)[3]), \
          "r"((bp)[0]), "r"((bp)[1]))

#define MBAR_INIT(a, c) \
    asm volatile("mbarrier.init.shared.b64 [%0], %1;" :: "r"(a), "r"((uint32_t)(c)) : "memory")
#define MBAR_EXPECT_TX(a, bytes) \
    asm volatile("mbarrier.arrive.expect_tx.shared.b64 _, [%0], %1;" \
                 :: "r"(a), "r"((uint32_t)(bytes)) : "memory")
#define BULK_G2S(dst, src, bytes, mbar) \
    asm volatile("cp.async.bulk.shared::cluster.global.mbarrier::complete_tx::bytes " \
                 "[%0], [%1], %2, [%3];" \
                 :: "r"(dst), "l"(src), "r"((uint32_t)(bytes)), "r"(mbar) : "memory")
#define MBAR_WAIT(mbar, parity) do { \
    uint32_t _m = (mbar), _p = (parity), _d; \
    asm volatile("{\n\t.reg .pred p;\n\t" \
        "mbarrier.try_wait.parity.shared.b64 p, [%1], %2;\n\t" \
        "selp.b32 %0, 1, 0, p;\n\t}" : "=r"(_d) : "r"(_m), "r"(_p) : "memory"); \
    if (!_d) { \
        asm volatile("{\n\t.reg .pred P1;\n\t" \
            "WL_%=:\n\t" \
            "mbarrier.try_wait.parity.shared.b64 P1, [%0], %1;\n\t" \
            "@P1 bra.uni WD_%=;\n\t" \
            "bra.uni WL_%=;\n\t" \
            "WD_%=:\n\t}" :: "r"(_m), "r"(_p) : "memory"); \
    } \
} while (0)

// padded chunk-major address of element (row, col) in an arena with kch chunks
__device__ __forceinline__ size_t pad_addr(int row, int col, int kch) {
    return (size_t)(row >> 7) * ((size_t)kch * CHUNK_B)
         + (size_t)(col >> 5) * CHUNK_B
         + (size_t)(row & 127) * 80 + (size_t)(((col & 31) >> 3) << 4) + (size_t)((col & 7) << 1);
}

// ---------------------------------------------------------------------------
// Device-global scratch (A-side arenas are padded chunk-major)
// ---------------------------------------------------------------------------
__device__ __align__(256) char g_nodef[(size_t)MT_MAX * 16 * CHUNK_B];
__device__ __align__(256) char g_molf[(size_t)16 * 16 * CHUNK_B];
__device__ __align__(256) char g_H[(size_t)MT_MAX * 24 * CHUNK_B];
__device__ __align__(256) char g_corrp[(size_t)MT_MAX * 4 * CHUNK_B];
__device__ __align__(256) __half g_KQV[(size_t)NPB_MAX * 384];
__device__ __align__(256) __half g_K2[(size_t)NPB_MAX * ATT];
__device__ __align__(256) __half g_Q2[(size_t)MAXB * ATT];
__device__ __align__(256) char  g_W[1802240];
__device__ __align__(256) float g_b1[768];
__device__ __align__(256) float g_b2[384];
__device__ float g_V0[ATT];
__device__ int   g_off[MAXB + 1];

// ---------------------------------------------------------------------------
// scan of batch_counts
// ---------------------------------------------------------------------------
__global__ void scan_kernel(const int* __restrict__ counts, int* __restrict__ offsets, int B)
{
    __shared__ int s[2048];
    int tid = threadIdx.x;
    for (int i = tid; i < B; i += 1024) s[i] = counts[i];
    __syncthreads();
    for (int d = 1; d < B; d <<= 1) {
        int i0 = tid, i1 = tid + 1024;
        int v0 = 0, v1 = 0;
        if (i0 < B && i0 >= d) v0 = s[i0 - d];
        if (i1 < B && i1 >= d) v1 = s[i1 - d];
        __syncthreads();
        if (i0 < B && i0 >= d) s[i0] += v0;
        if (i1 < B && i1 >= d) s[i1] += v1;
        __syncthreads();
    }
    for (int i = tid; i < B; i += 1024) offsets[i + 1] = s[i];
    if (tid == 0) offsets[0] = 0;
}

// V0 = relu(bv1) @ wv2 + bv2
__global__ void v0_kernel(const float* __restrict__ bv1, const float* __restrict__ wv2,
                          const float* __restrict__ bv2, float* __restrict__ V0)
{
    int t = threadIdx.x;
    float acc = bv2[t];
    #pragma unroll 8
    for (int h = 0; h < HID; h++) acc += fmaxf(bv1[h], 0.f) * wv2[h * ATT + t];
    V0[t] = acc;
}

// fp32 -> fp16 convert into padded chunk-major layout (16B group per thread)
__global__ void cvt_pad_kernel(const float* __restrict__ x, char* __restrict__ dst,
                               int M, int K)
{
    int groups = K >> 3;
    int idx = blockIdx.x * 256 + threadIdx.x;
    if (idx >= M * groups) return;
    int r = idx / groups, g = idx - r * groups;
    const float4* s = reinterpret_cast<const float4*>(x + (size_t)r * K + (size_t)g * 8);
    float4 v0 = s[0], v1 = s[1];
    __half2 p0 = __halves2half2(__float2half_rn(v0.x), __float2half_rn(v0.y));
    __half2 p1 = __halves2half2(__float2half_rn(v0.z), __float2half_rn(v0.w));
    __half2 p2 = __halves2half2(__float2half_rn(v1.x), __float2half_rn(v1.y));
    __half2 p3 = __halves2half2(__float2half_rn(v1.z), __float2half_rn(v1.w));
    uint4 u;
    u.x = reinterpret_cast<uint32_t&>(p0);
    u.y = reinterpret_cast<uint32_t&>(p1);
    u.z = reinterpret_cast<uint32_t&>(p2);
    u.w = reinterpret_cast<uint32_t&>(p3);
    int kch = K >> 5;
    size_t o = (size_t)(r >> 7) * ((size_t)kch * CHUNK_B) + (size_t)(g >> 2) * CHUNK_B
             + (size_t)(r & 127) * 80 + (size_t)(g & 3) * 16;
    *reinterpret_cast<uint4*>(dst + o) = u;
}

// ---------------------------------------------------------------------------
// Weights: transpose + quantize + pad into chunk-major smem-image layout.
// ---------------------------------------------------------------------------
struct WSpec { const float* w; int K; int N; int off; };   // off in BYTES
struct WTable { WSpec s[10]; };

__global__ void tsplit_all(WTable t, char* __restrict__ W)
{
    WSpec sp = t.s[blockIdx.y];
    int tot = sp.K * sp.N;
    int kch = sp.K >> 5;
    for (int i = blockIdx.x * 256 + threadIdx.x; i < tot; i += gridDim.x * 256) {
        int n = i / sp.K, k = i - n * sp.K;
        size_t o = (size_t)sp.off
                 + ((size_t)((n >> 7) * kch + (k >> 5))) * CHUNK_B
                 + (size_t)(n & 127) * 80 + ((k & 31) >> 3) * 16 + (k & 7) * 2;
        *reinterpret_cast<__half*>(W + o) = __float2half_rn(sp.w[(size_t)k * sp.N + n]);
    }
}

__global__ void bias_concat(const float* bk1, const float* bq1, const float* bv1,
                            const float* bk2, const float* bq2, const float* bv2,
                            float* __restrict__ b1, float* __restrict__ b2)
{
    int i = blockIdx.x * 256 + threadIdx.x;
    if (i < 768) {
        const float* src = (i < 256) ? bk1 : (i < 512) ? bq1 : bv1;
        b1[i] = src[i & 255];
    } else if (i < 1152) {
        int j = i - 768;
        const float* src = (j < 128) ? bk2 : (j < 256) ? bq2 : bv2;
        b2[j] = src[j & 127];
    }
}

// ---------------------------------------------------------------------------
// HMMA fp16 GEMM: CTA 128x128, 256 threads, 8 warps @ 32x64, SUPER-chunk
// K=64, 2-stage double buffer (40KB/stage), 2 CTAs/SM. One bulk copy per
// operand per super-chunk; one __syncthreads per super-chunk.
// ---------------------------------------------------------------------------
#define STG_A   0
#define STG_B   20480
#define STAGE_B 40960
#define GSMEM   81920           // 2 stages x 40KB

template <bool RELU>
__global__ __launch_bounds__(256, 2)
void mma_gemm(const char* __restrict__ Ab, const char* __restrict__ Wb,
              const float* __restrict__ bias, uint32_t* __restrict__ Cl,
              char* __restrict__ Cpad,
              int M, int K, int N, int ldaChunks, int aBlkChunks)
{
    extern __shared__ char smem[];
    __shared__ float sbias[128];
    __shared__ __align__(8) uint64_t mbars[2];
    const uint32_t sb = smem_u32(smem);
    const uint32_t mb = smem_u32(mbars);

    const int tid  = threadIdx.x;
    const int lane = tid & 31;
    const int wid  = tid >> 5;        // 0..7
    const int wm   = wid >> 1;        // 0..3 -> 32-row slice
    const int wn   = wid & 1;         // 0..1 -> 64-col slice
    const int m0   = blockIdx.x * 128;
    const int n0   = blockIdx.y * 128;
    const int nsc  = K / 64;          // super-chunks
    const int outkch = N / 32;

    if (tid < 128) sbias[tid] = bias[n0 + tid];
    if (tid == 0) {
        MBAR_INIT(mb + 0, 1);
        MBAR_INIT(mb + 8, 1);
    }
    __syncthreads();

    float acc[2][8][4];
    #pragma unroll
    for (int i = 0; i < 2; i++)
        #pragma unroll
        for (int j = 0; j < 8; j++)
            #pragma unroll
            for (int k = 0; k < 4; k++) acc[i][j][k] = 0.f;

    const char* abase = Ab + (size_t)blockIdx.x * ldaChunks * CHUNK_B
                           + (size_t)blockIdx.y * aBlkChunks * CHUNK_B;
    const char* wbase = Wb + (size_t)blockIdx.y * (K / 32) * CHUNK_B;

    auto stage = [&](int sc, int s) {
        if (tid == 0) {
            uint32_t base = sb + (uint32_t)s * STAGE_B;
            uint32_t mslot = mb + (uint32_t)s * 8;
            MBAR_EXPECT_TX(mslot, 4 * CHUNK_B);
            BULK_G2S(base + STG_A, abase + (size_t)sc * 2 * CHUNK_B, 2 * CHUNK_B, mslot);
            BULK_G2S(base + STG_B, wbase + (size_t)sc * 2 * CHUNK_B, 2 * CHUNK_B, mslot);
        }
    };

    auto compute = [&](int s) {
        uint32_t base = sb + (uint32_t)s * STAGE_B;
        #pragma unroll
        for (int sub = 0; sub < 2; sub++) {
            uint32_t aS = base + STG_A + (uint32_t)sub * CHUNK_B;
            uint32_t bS = base + STG_B + (uint32_t)sub * CHUNK_B;
            #pragma unroll
            for (int ks = 0; ks < 2; ks++) {
                const int kb = ks * 16;
                const uint32_t arow = (uint32_t)(wm * 32 + (lane & 15));
                const uint32_t acol = (uint32_t)((kb + ((lane >> 4) << 3)) * 2);
                const int bl8 = lane & 7, bseg = lane >> 3;
                const uint32_t brow = (uint32_t)(wn * 64 + ((bseg >> 1) << 3) + bl8);
                const uint32_t bcol = (uint32_t)((kb + ((bseg & 1) << 3)) * 2);

                uint32_t a[2][4], b[4][4];
                #pragma unroll
                for (int g = 0; g < 4; g++)    LDSM4(b[g], bS + (brow + g * 16) * 80 + bcol);
                #pragma unroll
                for (int mf = 0; mf < 2; mf++) LDSM4(a[mf], aS + (arow + mf * 16) * 80 + acol);
                #pragma unroll
                for (int mf = 0; mf < 2; mf++)
                    #pragma unroll
                    for (int nf = 0; nf < 8; nf++)
                        MMA16816(acc[mf][nf], a[mf], &b[nf >> 1][(nf & 1) * 2]);
            }
        }
    };

    stage(0, 0);
    for (int sc = 0; sc < nsc; sc++) {
        __syncthreads();                    // all warps done with slot (sc-1)&1
        if (sc + 1 < nsc) stage(sc + 1, (sc + 1) & 1);
        MBAR_WAIT(mb + (uint32_t)(sc & 1) * 8, (sc >> 1) & 1);
        compute(sc & 1);
    }

    #pragma unroll
    for (int mf = 0; mf < 2; mf++) {
        #pragma unroll
        for (int half = 0; half < 2; half++) {
            int gm = m0 + wm * 32 + mf * 16 + (lane >> 2) + half * 8;
            if (gm >= M) continue;
            #pragma unroll
            for (int nf = 0; nf < 8; nf++) {
                int cl = wn * 64 + nf * 8 + (lane & 3) * 2;
                float v0 = acc[mf][nf][half * 2 + 0] + sbias[cl];
                float v1 = acc[mf][nf][half * 2 + 1] + sbias[cl + 1];
                if (RELU) { v0 = fmaxf(v0, 0.f); v1 = fmaxf(v1, 0.f); }
                __half2 hp = __halves2half2(__float2half_rn(v0), __float2half_rn(v1));
                if (RELU) {
                    size_t o = (size_t)blockIdx.x * ((size_t)outkch * CHUNK_B)
                             + (size_t)((n0 + cl) >> 5) * CHUNK_B
                             + (size_t)(gm & 127) * 80
                             + (size_t)(((cl & 31) >> 3) << 4) + (size_t)((cl & 7) << 1);
                    *reinterpret_cast<uint32_t*>(Cpad + o) = reinterpret_cast<uint32_t&>(hp);
                } else {
                    size_t gi = (size_t)gm * N + (size_t)(n0 + cl);
                    Cl[gi >> 1] = reinterpret_cast<uint32_t&>(hp);
                }
            }
        }
    }
}

// ---------------------------------------------------------------------------
// Tensor-core attention; corr written padded chunk-major (4 kchunks).
// ---------------------------------------------------------------------------
#define AT_K 0
#define AT_Q 20480
#define AT_V 40960
#define AT_P 61440
#define AT_S 71680
#define AT_SMEM 89088

__global__ __launch_bounds__(256)
void attention_kernel(const __half* __restrict__ KQV, const float* __restrict__ V0,
                      const int* __restrict__ offsets, const int* __restrict__ counts,
                      char* __restrict__ corrp, int Ntot)
{
    extern __shared__ char smem[];
    const uint32_t sb = smem_u32(smem);
    float* S = (float*)(smem + AT_S);

    const int b    = blockIdx.x;
    const int m    = counts[b];
    const int off  = offsets[b];
    const int tid  = threadIdx.x;
    const int lane = tid & 31;
    const int wid  = tid >> 5;
    const int wm   = wid >> 1;
    const int wn   = wid & 1;
    const float scale = 0.08838834764831845f;

    const uint4 zero4 = make_uint4(0, 0, 0, 0);
    #pragma unroll
    for (int it = 0; it < 4; it++) {
        int idx = tid + it * 256;
        int r = idx >> 4, g = idx & 15;
        int ch = g >> 2, q = g & 3;
        uint32_t so = (uint32_t)ch * 5120 + (uint32_t)r * 80 + (uint32_t)q * 16;
        uint4 kv = zero4, qv = zero4;
        if (r < m) {
            size_t gbase = (size_t)(off + r) * 384 + (size_t)ch * 32 + (size_t)q * 8;
            kv = *reinterpret_cast<const uint4*>(KQV + gbase);
            qv = *reinterpret_cast<const uint4*>(KQV + gbase + 128);
        }
        *reinterpret_cast<uint4*>(smem + AT_K + so) = kv;
        *reinterpret_cast<uint4*>(smem + AT_Q + so) = qv;
    }
    #pragma unroll
    for (int it = 0; it < 32; it++) {
        int idx = tid + it * 256;
        int j = idx >> 7, d = idx & 127;
        __half v = (j < m) ? KQV[(size_t)(off + j) * 384 + 256 + d] : __float2half_rn(0.f);
        uint32_t so = (uint32_t)(j >> 5) * 10240 + (uint32_t)d * 80
                    + (uint32_t)(((j & 31) >> 3) << 4) + (uint32_t)((j & 7) << 1);
        *reinterpret_cast<__half*>(smem + AT_V + so) = v;
    }
    __syncthreads();

    {
        float accS[4][4];
        #pragma unroll
        for (int i = 0; i < 4; i++)
            #pragma unroll
            for (int k = 0; k < 4; k++) accS[i][k] = 0.f;

        #pragma unroll
        for (int ch = 0; ch < 4; ch++) {
            #pragma unroll
            for (int ks = 0; ks < 2; ks++) {
                const int kb = ks * 16;
                const uint32_t arow = (uint32_t)(wm * 16 + (lane & 15));
                const uint32_t acol = (uint32_t)((kb + ((lane >> 4) << 3)) * 2);
                const int bl8 = lane & 7, bseg = lane >> 3;
                const uint32_t brow = (uint32_t)(wn * 32 + ((bseg >> 1) << 3) + bl8);
                const uint32_t bcol = (uint32_t)((kb + ((bseg & 1) << 3)) * 2);
                uint32_t a[4], bf[2][4];
                LDSM4(a, sb + AT_K + ch * 5120 + arow * 80 + acol);
                #pragma unroll
                for (int g = 0; g < 2; g++)
                    LDSM4(bf[g], sb + AT_Q + ch * 5120 + (brow + g * 16) * 80 + bcol);
                #pragma unroll
                for (int nf = 0; nf < 4; nf++)
                    MMA16816(accS[nf], a, &bf[nf >> 1][(nf & 1) * 2]);
            }
        }
        #pragma unroll
        for (int nf = 0; nf < 4; nf++)
            #pragma unroll
            for (int e = 0; e < 4; e++) {
                int row = wm * 16 + (lane >> 2) + ((e >> 1) ? 8 : 0);
                int col = wn * 32 + nf * 8 + (lane & 3) * 2 + (e & 1);
                S[row * 68 + col] = accS[nf][e] * scale;
            }
    }
    __syncthreads();

    for (int i = wid; i < 64; i += 8) {
        float p0 = 0.f, p1 = 0.f;
        if (i < m) {
            float v0 = (lane      < m) ? S[i * 68 + lane]      : -3.4e38f;
            float v1 = (lane + 32 < m) ? S[i * 68 + lane + 32] : -3.4e38f;
            float mx = fmaxf(v0, v1);
            #pragma unroll
            for (int o = 16; o; o >>= 1) mx = fmaxf(mx, __shfl_xor_sync(0xffffffffu, mx, o));
            float e0 = (lane      < m) ? __expf(v0 - mx) : 0.f;
            float e1 = (lane + 32 < m) ? __expf(v1 - mx) : 0.f;
            float sum = e0 + e1;
            #pragma unroll
            for (int o = 16; o; o >>= 1) sum += __shfl_xor_sync(0xffffffffu, sum, o);
            float inv = 1.f / sum;
            p0 = e0 * inv; p1 = e1 * inv;
        }
        uint32_t so = (uint32_t)i * 80 + (uint32_t)((lane >> 3) << 4) + (uint32_t)((lane & 7) << 1);
        *reinterpret_cast<__half*>(smem + AT_P + so)        = __float2half_rn(p0);
        *reinterpret_cast<__half*>(smem + AT_P + 5120 + so) = __float2half_rn(p1);
    }
    __syncthreads();

    {
        float accC[8][4];
        #pragma unroll
        for (int j = 0; j < 8; j++)
            #pragma unroll
            for (int k = 0; k < 4; k++) accC[j][k] = 0.f;

        #pragma unroll
        for (int ch = 0; ch < 2; ch++) {
            #pragma unroll
            for (int ks = 0; ks < 2; ks++) {
                const int kb = ks * 16;
                const uint32_t arow = (uint32_t)(wm * 16 + (lane & 15));
                const uint32_t acol = (uint32_t)((kb + ((lane >> 4) << 3)) * 2);
                const int bl8 = lane & 7, bseg = lane >> 3;
                const uint32_t brow = (uint32_t)(wn * 64 + ((bseg >> 1) << 3) + bl8);
                const uint32_t bcol = (uint32_t)((kb + ((bseg & 1) << 3)) * 2);
                uint32_t a[4], bf[4][4];
                LDSM4(a, sb + AT_P + ch * 5120 + arow * 80 + acol);
                #pragma unroll
                for (int g = 0; g < 4; g++)
                    LDSM4(bf[g], sb + AT_V + ch * 10240 + (brow + g * 16) * 80 + bcol);
                #pragma unroll
                for (int nf = 0; nf < 8; nf++)
                    MMA16816(accC[nf], a, &bf[nf >> 1][(nf & 1) * 2]);
            }
        }
        #pragma unroll
        for (int half = 0; half < 2; half++) {
            int row = wm * 16 + (lane >> 2) + half * 8;
            if (row < m) {
                int gr = off + row;
                #pragma unroll
                for (int nf = 0; nf < 8; nf++) {
                    int col = wn * 64 + nf * 8 + (lane & 3) * 2;
                    __half2 hp = __halves2half2(__float2half_rn(accC[nf][half * 2]),
                                                __float2half_rn(accC[nf][half * 2 + 1]));
                    *reinterpret_cast<uint32_t*>(corrp + pad_addr(gr, col, 4))
                        = reinterpret_cast<uint32_t&>(hp);
                }
            }
        }
    }

    if (tid < ATT) {
        int d = tid;
        float a = 0.f;
        for (int j = 0; j < m; j++) {
            uint32_t so = (uint32_t)(j >> 5) * 10240 + (uint32_t)d * 80
                        + (uint32_t)(((j & 31) >> 3) << 4) + (uint32_t)((j & 7) << 1);
            a += __half2float(*reinterpret_cast<__half*>(smem + AT_V + so));
        }
        a = (a + (float)(MAXA - m) * V0[d]) * 0.02f;
        *reinterpret_cast<__half*>(corrp + pad_addr(Ntot + b, d, 4)) = __float2half_rn(a);
    }
}

// ---------------------------------------------------------------------------
// logits -> cs MLP -> sigmoid -> ragged scatter (K2, Q2 fp16 linear)
// ---------------------------------------------------------------------------
__global__ void final_kernel(const __half* __restrict__ K2, const __half* __restrict__ Q2,
                             const int* __restrict__ offsets, const int* __restrict__ counts,
                             const float* __restrict__ cs1, const float* __restrict__ bcs1,
                             const float* __restrict__ cs2, const float* __restrict__ bcs2,
                             float* __restrict__ out, int Ntot)
{
    __shared__ float q2s[ATT];
    __shared__ float lg[MAXA];
    __shared__ float hs[ATT];

    const int b   = blockIdx.x;
    const int tid = threadIdx.x;
    const int m   = counts[b];
    const int off = offsets[b];
    const float scale = 0.08838834764831845f;

    q2s[tid] = __half2float(Q2[(size_t)b * ATT + tid]);
    __syncthreads();

    const int warp = tid >> 5, lane = tid & 31;
    for (int i = warp; i < MAXA; i += 4) {
        const __half* row = (i < m) ? (K2 + (size_t)(off + i) * ATT)
                                    : (K2 + (size_t)(Ntot + b) * ATT);
        float a = 0.f;
        #pragma unroll
        for (int c = 0; c < 4; c++) {
            int d = lane + c * 32;
            a += __half2float(row[d]) * q2s[d];
        }
        #pragma unroll
        for (int o = 16; o; o >>= 1) a += __shfl_xor_sync(0xffffffffu, a, o);
        if (lane == 0) lg[i] = a * scale;
    }
    __syncthreads();

    {
        float a = bcs1[tid];
        #pragma unroll
        for (int i = 0; i < MAXA; i++) a += lg[i] * cs1[i * ATT + tid];
        hs[tid] = fmaxf(a, 0.f);
    }
    __syncthreads();

    if (tid < MAXA) {
        float a = bcs2[tid];
        #pragma unroll 16
        for (int h = 0; h < ATT; h++) a += hs[h] * cs2[h * MAXA + tid];
        float sel = 1.f / (1.f + __expf(-a));
        if (tid < m) out[off + tid] = sel;
    }
}

// ---------------------------------------------------------------------------
// Host launcher
// ---------------------------------------------------------------------------
static inline void launch_gemm(bool relu,
                               const char* Ab, const char* Wb,
                               const float* bias, void* Cl, char* Cpad,
                               int M, int K, int N, int ldaChunks, int aBlkChunks)
{
    dim3 grid((M + 127) / 128, N / 128);
    if (relu)
        mma_gemm<true><<<grid, 256, GSMEM>>>(Ab, Wb, bias, (uint32_t*)Cl, Cpad,
                                             M, K, N, ldaChunks, aBlkChunks);
    else
        mma_gemm<false><<<grid, 256, GSMEM>>>(Ab, Wb, bias, (uint32_t*)Cl, Cpad,
                                              M, K, N, ldaChunks, aBlkChunks);
}

extern "C" void kernel_launch(void* const* d_in, const int* in_sizes, int n_in,
                              void* d_out, int out_size)
{
    const float* mol_a  = (const float*)d_in[0];
    const float* node   = (const float*)d_in[1];
    const int*   counts = (const int*)  d_in[2];
    const float* wq1 = (const float*)d_in[3],  *bq1 = (const float*)d_in[4];
    const float* wq2 = (const float*)d_in[5],  *bq2 = (const float*)d_in[6];
    const float* wk1 = (const float*)d_in[7],  *bk1 = (const float*)d_in[8];
    const float* wk2 = (const float*)d_in[9],  *bk2 = (const float*)d_in[10];
    const float* wv1 = (const float*)d_in[11], *bv1 = (const float*)d_in[12];
    const float* wv2 = (const float*)d_in[13], *bv2 = (const float*)d_in[14];
    const float* uk1 = (const float*)d_in[15], *ubk1 = (const float*)d_in[16];
    const float* uk2 = (const float*)d_in[17], *ubk2 = (const float*)d_in[18];
    const float* uq1 = (const float*)d_in[19], *ubq1 = (const float*)d_in[20];
    const float* uq2 = (const float*)d_in[21], *ubq2 = (const float*)d_in[22];
    const float* cs1 = (const float*)d_in[23], *bcs1 = (const float*)d_in[24];
    const float* cs2 = (const float*)d_in[25], *bcs2 = (const float*)d_in[26];
    float* out = (float*)d_out;

    const int N = in_sizes[1] / 512;
    const int B = in_sizes[2];
    const int NPB = N + B;

    char *nodef, *molf, *H, *corrp, *W;
    __half *KQV, *K2, *Q2;
    float *V0, *b1, *b2;
    int* off;
    cudaGetSymbolAddress((void**)&nodef, g_nodef);
    cudaGetSymbolAddress((void**)&molf,  g_molf);
    cudaGetSymbolAddress((void**)&H,     g_H);
    cudaGetSymbolAddress((void**)&corrp, g_corrp);
    cudaGetSymbolAddress((void**)&KQV,   g_KQV);
    cudaGetSymbolAddress((void**)&K2,    g_K2);
    cudaGetSymbolAddress((void**)&Q2,    g_Q2);
    cudaGetSymbolAddress((void**)&W,     g_W);
    cudaGetSymbolAddress((void**)&V0,    g_V0);
    cudaGetSymbolAddress((void**)&b1,    g_b1);
    cudaGetSymbolAddress((void**)&b2,    g_b2);
    cudaGetSymbolAddress((void**)&off,   g_off);

    cudaFuncSetAttribute((const void*)mma_gemm<true>,
                         cudaFuncAttributeMaxDynamicSharedMemorySize, GSMEM);
    cudaFuncSetAttribute((const void*)mma_gemm<false>,
                         cudaFuncAttributeMaxDynamicSharedMemorySize, GSMEM);
    cudaFuncSetAttribute(attention_kernel,
                         cudaFuncAttributeMaxDynamicSharedMemorySize, AT_SMEM);

    // chunk-major padded weight arena (byte offsets); W1cat / W2cat contiguous
    const int o_wk1 = 0,        o_wq1 = 327680,   o_wv1 = 655360;   // [768,512]
    const int o_wk2 = 983040,   o_wq2 = 1064960,  o_wv2 = 1146880;  // [384,256]
    const int o_uk1 = 1228800,  o_uk2 = 1310720;
    const int o_uq1 = 1392640,  o_uq2 = 1720320;

    scan_kernel<<<1, 1024>>>(counts, off, B);
    v0_kernel<<<1, ATT>>>(bv1, wv2, bv2, V0);
    bias_concat<<<5, 256>>>(bk1, bq1, bv1, bk2, bq2, bv2, b1, b2);

    {
        int ng = N * 64;
        cvt_pad_kernel<<<(ng + 255) / 256, 256>>>(node, nodef, N, 512);
        int mg = B * 64;
        cvt_pad_kernel<<<(mg + 255) / 256, 256>>>(mol_a, molf, B, 512);
    }

    {
        WTable t;
        t.s[0] = {wk1, 512, 256, o_wk1}; t.s[1] = {wq1, 512, 256, o_wq1};
        t.s[2] = {wv1, 512, 256, o_wv1}; t.s[3] = {wk2, 256, 128, o_wk2};
        t.s[4] = {wq2, 256, 128, o_wq2}; t.s[5] = {wv2, 256, 128, o_wv2};
        t.s[6] = {uk1, 128, 256, o_uk1}; t.s[7] = {uk2, 256, 128, o_uk2};
        t.s[8] = {uq1, 512, 256, o_uq1}; t.s[9] = {uq2, 256, 128, o_uq2};
        dim3 g(128, 10);
        tsplit_all<<<g, 256>>>(t, W);
    }

    // Q2 = mlp2(mol_a):  molf (16 kch) -> H padded (8 kch) -> Q2 linear
    launch_gemm(true,  molf, W + o_uq1, ubq1, nullptr, H, B, 512, 256, 16, 0);
    launch_gemm(false, H,    W + o_uq2, ubq2, Q2, nullptr, B, 256, 128, 8, 0);

    // fused KQV layer1: nodef (16 kch) -> H padded (24 kch)
    launch_gemm(true,  nodef, W + o_wk1, b1, nullptr, H, N, 512, 768, 16, 0);
    // fused KQV layer2 (block-diagonal): H kch offset 8 per 128-col N block -> KQV linear
    launch_gemm(false, H, W + o_wk2, b2, KQV, nullptr, N, 256, 384, 24, 8);

    // tensor-core attention -> corr padded (4 kch)
    attention_kernel<<<B, 256, AT_SMEM>>>(KQV, V0, off, counts, corrp, N);

    // K2 = mlp2(corr) over N+B rows: corrp (4 kch) -> H padded (8 kch) -> K2 linear
    launch_gemm(true,  corrp, W + o_uk1, ubk1, nullptr, H, NPB, 128, 256, 4, 0);
    launch_gemm(false, H,     W + o_uk2, ubk2, K2, nullptr, NPB, 256, 128, 8, 0);

    final_kernel<<<B, 128>>>(K2, Q2, off, counts, cs1, bcs1, cs2, bcs2, out, N);
}

// round 16
// speedup vs baseline: 1.1638x; 1.1638x over previous
#include <cuda_runtime.h>
#include <cuda_fp16.h>
#include <math.h>
#include <cstdint>

// ---------------------------------------------------------------------------
// B=2048, D=512, ATT=128, HID=256, MAX_ATOMS=50. N = 52176 at runtime.
// Single-pass fp16 HMMA. GEMM: 128x128 CTA, 256 thr, 3-stage (32-K chunks),
// 2 CTAs/SM, bulk-copy staging (round-12 config, known good).
// NEW: dual-stream graph-captured overlap of the independent preprocessing
// branch (scan/v0/cvt_mol + Q2 GEMMs into a dedicated H2 arena).
// ---------------------------------------------------------------------------
#define MAXB     2048
#define NPB_MAX  56320          // >= N + B rows
#define ATT      128
#define HID      256
#define MAXA     50
#define MT_MAX   440            // max 128-row tiles
#define CHUNK_B  10240          // one 32-K chunk image: 128 rows x 80 B

// ---------------------------------------------------------------------------
// PTX helpers (<= sm_90 non-'a' features only)
// ---------------------------------------------------------------------------
__device__ __forceinline__ uint32_t smem_u32(const void* p) {
    uint32_t a;
    asm("{ .reg .u64 t; cvta.to.shared.u64 t, %1; cvt.u32.u64 %0, t; }" : "=r"(a) : "l"(p));
    return a;
}

#define LDSM4(r, addr) \
    asm volatile("ldmatrix.sync.aligned.m8n8.x4.shared.b16 {%0,%1,%2,%3}, [%4];" \
        : "=r"((r)[0]), "=r"((r)[1]), "=r"((r)[2]), "=r"((r)[3]) : "r"(addr))

#define MMA16816(d, a, bp) \
    asm volatile("mma.sync.aligned.m16n8k16.row.col.f32.f16.f16.f32 " \
        "{%0,%1,%2,%3}, {%4,%5,%6,%7}, {%8,%9}, {%0,%1,%2,%3};" \
        : "+f"((d)[0]), "+f"((d)[1]), "+f"((d)[2]), "+f"((d)[3]) \
        : "r"((a)[0]), "r"((a)[1]), "r"((a)[2]), "r"((a)[3]), \
          "r"((bp)[0]), "r"((bp)[1]))

#define MBAR_INIT(a, c) \
    asm volatile("mbarrier.init.shared.b64 [%0], %1;" :: "r"(a), "r"((uint32_t)(c)) : "memory")
#define MBAR_EXPECT_TX(a, bytes) \
    asm volatile("mbarrier.arrive.expect_tx.shared.b64 _, [%0], %1;" \
                 :: "r"(a), "r"((uint32_t)(bytes)) : "memory")
#define BULK_G2S(dst, src, bytes, mbar) \
    asm volatile("cp.async.bulk.shared::cluster.global.mbarrier::complete_tx::bytes " \
                 "[%0], [%1], %2, [%3];" \
                 :: "r"(dst), "l"(src), "r"((uint32_t)(bytes)), "r"(mbar) : "memory")
#define MBAR_WAIT(mbar, parity) do { \
    uint32_t _m = (mbar), _p = (parity), _d; \
    asm volatile("{\n\t.reg .pred p;\n\t" \
        "mbarrier.try_wait.parity.shared.b64 p, [%1], %2;\n\t" \
        "selp.b32 %0, 1, 0, p;\n\t}" : "=r"(_d) : "r"(_m), "r"(_p) : "memory"); \
    if (!_d) { \
        asm volatile("{\n\t.reg .pred P1;\n\t" \
            "WL_%=:\n\t" \
            "mbarrier.try_wait.parity.shared.b64 P1, [%0], %1;\n\t" \
            "@P1 bra.uni WD_%=;\n\t" \
            "bra.uni WL_%=;\n\t" \
            "WD_%=:\n\t}" :: "r"(_m), "r"(_p) : "memory"); \
    } \
} while (0)

// padded chunk-major address of element (row, col) in an arena with kch chunks
__device__ __forceinline__ size_t pad_addr(int row, int col, int kch) {
    return (size_t)(row >> 7) * ((size_t)kch * CHUNK_B)
         + (size_t)(col >> 5) * CHUNK_B
         + (size_t)(row & 127) * 80 + (size_t)(((col & 31) >> 3) << 4) + (size_t)((col & 7) << 1);
}

// ---------------------------------------------------------------------------
// Device-global scratch (A-side arenas are padded chunk-major)
// ---------------------------------------------------------------------------
__device__ __align__(256) char g_nodef[(size_t)MT_MAX * 16 * CHUNK_B];
__device__ __align__(256) char g_molf[(size_t)16 * 16 * CHUNK_B];
__device__ __align__(256) char g_H[(size_t)MT_MAX * 24 * CHUNK_B];
__device__ __align__(256) char g_H2[(size_t)16 * 8 * CHUNK_B];     // Q2-branch hidden
__device__ __align__(256) char g_corrp[(size_t)MT_MAX * 4 * CHUNK_B];
__device__ __align__(256) __half g_KQV[(size_t)NPB_MAX * 384];
__device__ __align__(256) __half g_K2[(size_t)NPB_MAX * ATT];
__device__ __align__(256) __half g_Q2[(size_t)MAXB * ATT];
__device__ __align__(256) char  g_W[1802240];
__device__ __align__(256) float g_b1[768];
__device__ __align__(256) float g_b2[384];
__device__ float g_V0[ATT];
__device__ int   g_off[MAXB + 1];

// ---------------------------------------------------------------------------
// scan of batch_counts
// ---------------------------------------------------------------------------
__global__ void scan_kernel(const int* __restrict__ counts, int* __restrict__ offsets, int B)
{
    __shared__ int s[2048];
    int tid = threadIdx.x;
    for (int i = tid; i < B; i += 1024) s[i] = counts[i];
    __syncthreads();
    for (int d = 1; d < B; d <<= 1) {
        int i0 = tid, i1 = tid + 1024;
        int v0 = 0, v1 = 0;
        if (i0 < B && i0 >= d) v0 = s[i0 - d];
        if (i1 < B && i1 >= d) v1 = s[i1 - d];
        __syncthreads();
        if (i0 < B && i0 >= d) s[i0] += v0;
        if (i1 < B && i1 >= d) s[i1] += v1;
        __syncthreads();
    }
    for (int i = tid; i < B; i += 1024) offsets[i + 1] = s[i];
    if (tid == 0) offsets[0] = 0;
}

// V0 = relu(bv1) @ wv2 + bv2
__global__ void v0_kernel(const float* __restrict__ bv1, const float* __restrict__ wv2,
                          const float* __restrict__ bv2, float* __restrict__ V0)
{
    int t = threadIdx.x;
    float acc = bv2[t];
    #pragma unroll 8
    for (int h = 0; h < HID; h++) acc += fmaxf(bv1[h], 0.f) * wv2[h * ATT + t];
    V0[t] = acc;
}

// fp32 -> fp16 convert into padded chunk-major layout (16B group per thread)
__global__ void cvt_pad_kernel(const float* __restrict__ x, char* __restrict__ dst,
                               int M, int K)
{
    int groups = K >> 3;
    int idx = blockIdx.x * 256 + threadIdx.x;
    if (idx >= M * groups) return;
    int r = idx / groups, g = idx - r * groups;
    const float4* s = reinterpret_cast<const float4*>(x + (size_t)r * K + (size_t)g * 8);
    float4 v0 = s[0], v1 = s[1];
    __half2 p0 = __halves2half2(__float2half_rn(v0.x), __float2half_rn(v0.y));
    __half2 p1 = __halves2half2(__float2half_rn(v0.z), __float2half_rn(v0.w));
    __half2 p2 = __halves2half2(__float2half_rn(v1.x), __float2half_rn(v1.y));
    __half2 p3 = __halves2half2(__float2half_rn(v1.z), __float2half_rn(v1.w));
    uint4 u;
    u.x = reinterpret_cast<uint32_t&>(p0);
    u.y = reinterpret_cast<uint32_t&>(p1);
    u.z = reinterpret_cast<uint32_t&>(p2);
    u.w = reinterpret_cast<uint32_t&>(p3);
    int kch = K >> 5;
    size_t o = (size_t)(r >> 7) * ((size_t)kch * CHUNK_B) + (size_t)(g >> 2) * CHUNK_B
             + (size_t)(r & 127) * 80 + (size_t)(g & 3) * 16;
    *reinterpret_cast<uint4*>(dst + o) = u;
}

// ---------------------------------------------------------------------------
// Weights: transpose + quantize + pad into chunk-major smem-image layout.
// ---------------------------------------------------------------------------
struct WSpec { const float* w; int K; int N; int off; };   // off in BYTES
struct WTable { WSpec s[10]; };

__global__ void tsplit_all(WTable t, char* __restrict__ W)
{
    WSpec sp = t.s[blockIdx.y];
    int tot = sp.K * sp.N;
    int kch = sp.K >> 5;
    for (int i = blockIdx.x * 256 + threadIdx.x; i < tot; i += gridDim.x * 256) {
        int n = i / sp.K, k = i - n * sp.K;
        size_t o = (size_t)sp.off
                 + ((size_t)((n >> 7) * kch + (k >> 5))) * CHUNK_B
                 + (size_t)(n & 127) * 80 + ((k & 31) >> 3) * 16 + (k & 7) * 2;
        *reinterpret_cast<__half*>(W + o) = __float2half_rn(sp.w[(size_t)k * sp.N + n]);
    }
}

__global__ void bias_concat(const float* bk1, const float* bq1, const float* bv1,
                            const float* bk2, const float* bq2, const float* bv2,
                            float* __restrict__ b1, float* __restrict__ b2)
{
    int i = blockIdx.x * 256 + threadIdx.x;
    if (i < 768) {
        const float* src = (i < 256) ? bk1 : (i < 512) ? bq1 : bv1;
        b1[i] = src[i & 255];
    } else if (i < 1152) {
        int j = i - 768;
        const float* src = (j < 128) ? bk2 : (j < 256) ? bq2 : bv2;
        b2[j] = src[j & 127];
    }
}

// ---------------------------------------------------------------------------
// HMMA fp16 GEMM (round-12 config): CTA 128x128, 256 threads, 8 warps @
// 32x64, K-chunk 32, 3-stage, 2 CTAs/SM. Both operands staged by one
// cp.async.bulk each + single mbarrier (expect_tx 20480).
// ---------------------------------------------------------------------------
#define STG_A   0
#define STG_B   10240
#define STAGE_B 20480
#define GSMEM   61440           // 3 stages x 20KB

template <bool RELU>
__global__ __launch_bounds__(256, 2)
void mma_gemm(const char* __restrict__ Ab, const char* __restrict__ Wb,
              const float* __restrict__ bias, uint32_t* __restrict__ Cl,
              char* __restrict__ Cpad,
              int M, int K, int N, int ldaChunks, int aBlkChunks)
{
    extern __shared__ char smem[];
    __shared__ float sbias[128];
    __shared__ __align__(8) uint64_t mbars[3];
    const uint32_t sb = smem_u32(smem);
    const uint32_t mb = smem_u32(mbars);

    const int tid  = threadIdx.x;
    const int lane = tid & 31;
    const int wid  = tid >> 5;        // 0..7
    const int wm   = wid >> 1;        // 0..3 -> 32-row slice
    const int wn   = wid & 1;         // 0..1 -> 64-col slice
    const int m0   = blockIdx.x * 128;
    const int n0   = blockIdx.y * 128;
    const int nch  = K / 32;
    const int outkch = N / 32;

    if (tid < 128) sbias[tid] = bias[n0 + tid];
    if (tid == 0) {
        MBAR_INIT(mb + 0, 1);
        MBAR_INIT(mb + 8, 1);
        MBAR_INIT(mb + 16, 1);
    }
    __syncthreads();

    float acc[2][8][4];
    #pragma unroll
    for (int i = 0; i < 2; i++)
        #pragma unroll
        for (int j = 0; j < 8; j++)
            #pragma unroll
            for (int k = 0; k < 4; k++) acc[i][j][k] = 0.f;

    const char* abase = Ab + (size_t)blockIdx.x * ldaChunks * CHUNK_B
                           + (size_t)blockIdx.y * aBlkChunks * CHUNK_B;
    const char* wbase = Wb + (size_t)blockIdx.y * nch * CHUNK_B;

    auto stage = [&](int kc, int s) {
        if (tid == 0) {
            uint32_t base = sb + (uint32_t)s * STAGE_B;
            uint32_t mslot = mb + (uint32_t)s * 8;
            MBAR_EXPECT_TX(mslot, 2 * CHUNK_B);
            BULK_G2S(base + STG_A, abase + (size_t)kc * CHUNK_B, CHUNK_B, mslot);
            BULK_G2S(base + STG_B, wbase + (size_t)kc * CHUNK_B, CHUNK_B, mslot);
        }
    };

    auto compute = [&](int s) {
        uint32_t base = sb + (uint32_t)s * STAGE_B;
        uint32_t aS = base + STG_A, bS = base + STG_B;
        #pragma unroll
        for (int ks = 0; ks < 2; ks++) {
            const int kb = ks * 16;
            const uint32_t arow = (uint32_t)(wm * 32 + (lane & 15));
            const uint32_t acol = (uint32_t)((kb + ((lane >> 4) << 3)) * 2);
            const int bl8 = lane & 7, bseg = lane >> 3;
            const uint32_t brow = (uint32_t)(wn * 64 + ((bseg >> 1) << 3) + bl8);
            const uint32_t bcol = (uint32_t)((kb + ((bseg & 1) << 3)) * 2);

            uint32_t a[2][4], b[4][4];
            #pragma unroll
            for (int g = 0; g < 4; g++)    LDSM4(b[g], bS + (brow + g * 16) * 80 + bcol);
            #pragma unroll
            for (int mf = 0; mf < 2; mf++) LDSM4(a[mf], aS + (arow + mf * 16) * 80 + acol);
            #pragma unroll
            for (int mf = 0; mf < 2; mf++)
                #pragma unroll
                for (int nf = 0; nf < 8; nf++)
                    MMA16816(acc[mf][nf], a[mf], &b[nf >> 1][(nf & 1) * 2]);
        }
    };

    stage(0, 0);
    if (nch > 1) stage(1, 1);
    for (int kc = 0; kc < nch; kc++) {
        __syncthreads();                           // all warps done with slot (kc-1)%3
        if (kc + 2 < nch) stage(kc + 2, (kc + 2) % 3);
        MBAR_WAIT(mb + (uint32_t)(kc % 3) * 8, (kc / 3) & 1);
        compute(kc % 3);
    }

    #pragma unroll
    for (int mf = 0; mf < 2; mf++) {
        #pragma unroll
        for (int half = 0; half < 2; half++) {
            int gm = m0 + wm * 32 + mf * 16 + (lane >> 2) + half * 8;
            if (gm >= M) continue;
            #pragma unroll
            for (int nf = 0; nf < 8; nf++) {
                int cl = wn * 64 + nf * 8 + (lane & 3) * 2;
                float v0 = acc[mf][nf][half * 2 + 0] + sbias[cl];
                float v1 = acc[mf][nf][half * 2 + 1] + sbias[cl + 1];
                if (RELU) { v0 = fmaxf(v0, 0.f); v1 = fmaxf(v1, 0.f); }
                __half2 hp = __halves2half2(__float2half_rn(v0), __float2half_rn(v1));
                if (RELU) {
                    size_t o = (size_t)blockIdx.x * ((size_t)outkch * CHUNK_B)
                             + (size_t)((n0 + cl) >> 5) * CHUNK_B
                             + (size_t)(gm & 127) * 80
                             + (size_t)(((cl & 31) >> 3) << 4) + (size_t)((cl & 7) << 1);
                    *reinterpret_cast<uint32_t*>(Cpad + o) = reinterpret_cast<uint32_t&>(hp);
                } else {
                    size_t gi = (size_t)gm * N + (size_t)(n0 + cl);
                    Cl[gi >> 1] = reinterpret_cast<uint32_t&>(hp);
                }
            }
        }
    }
}

// ---------------------------------------------------------------------------
// Tensor-core attention; corr written padded chunk-major (4 kchunks).
// ---------------------------------------------------------------------------
#define AT_K 0
#define AT_Q 20480
#define AT_V 40960
#define AT_P 61440
#define AT_S 71680
#define AT_SMEM 89088

__global__ __launch_bounds__(256)
void attention_kernel(const __half* __restrict__ KQV, const float* __restrict__ V0,
                      const int* __restrict__ offsets, const int* __restrict__ counts,
                      char* __restrict__ corrp, int Ntot)
{
    extern __shared__ char smem[];
    const uint32_t sb = smem_u32(smem);
    float* S = (float*)(smem + AT_S);

    const int b    = blockIdx.x;
    const int m    = counts[b];
    const int off  = offsets[b];
    const int tid  = threadIdx.x;
    const int lane = tid & 31;
    const int wid  = tid >> 5;
    const int wm   = wid >> 1;
    const int wn   = wid & 1;
    const float scale = 0.08838834764831845f;

    const uint4 zero4 = make_uint4(0, 0, 0, 0);
    #pragma unroll
    for (int it = 0; it < 4; it++) {
        int idx = tid + it * 256;
        int r = idx >> 4, g = idx & 15;
        int ch = g >> 2, q = g & 3;
        uint32_t so = (uint32_t)ch * 5120 + (uint32_t)r * 80 + (uint32_t)q * 16;
        uint4 kv = zero4, qv = zero4;
        if (r < m) {
            size_t gbase = (size_t)(off + r) * 384 + (size_t)ch * 32 + (size_t)q * 8;
            kv = *reinterpret_cast<const uint4*>(KQV + gbase);
            qv = *reinterpret_cast<const uint4*>(KQV + gbase + 128);
        }
        *reinterpret_cast<uint4*>(smem + AT_K + so) = kv;
        *reinterpret_cast<uint4*>(smem + AT_Q + so) = qv;
    }
    #pragma unroll
    for (int it = 0; it < 32; it++) {
        int idx = tid + it * 256;
        int j = idx >> 7, d = idx & 127;
        __half v = (j < m) ? KQV[(size_t)(off + j) * 384 + 256 + d] : __float2half_rn(0.f);
        uint32_t so = (uint32_t)(j >> 5) * 10240 + (uint32_t)d * 80
                    + (uint32_t)(((j & 31) >> 3) << 4) + (uint32_t)((j & 7) << 1);
        *reinterpret_cast<__half*>(smem + AT_V + so) = v;
    }
    __syncthreads();

    {
        float accS[4][4];
        #pragma unroll
        for (int i = 0; i < 4; i++)
            #pragma unroll
            for (int k = 0; k < 4; k++) accS[i][k] = 0.f;

        #pragma unroll
        for (int ch = 0; ch < 4; ch++) {
            #pragma unroll
            for (int ks = 0; ks < 2; ks++) {
                const int kb = ks * 16;
                const uint32_t arow = (uint32_t)(wm * 16 + (lane & 15));
                const uint32_t acol = (uint32_t)((kb + ((lane >> 4) << 3)) * 2);
                const int bl8 = lane & 7, bseg = lane >> 3;
                const uint32_t brow = (uint32_t)(wn * 32 + ((bseg >> 1) << 3) + bl8);
                const uint32_t bcol = (uint32_t)((kb + ((bseg & 1) << 3)) * 2);
                uint32_t a[4], bf[2][4];
                LDSM4(a, sb + AT_K + ch * 5120 + arow * 80 + acol);
                #pragma unroll
                for (int g = 0; g < 2; g++)
                    LDSM4(bf[g], sb + AT_Q + ch * 5120 + (brow + g * 16) * 80 + bcol);
                #pragma unroll
                for (int nf = 0; nf < 4; nf++)
                    MMA16816(accS[nf], a, &bf[nf >> 1][(nf & 1) * 2]);
            }
        }
        #pragma unroll
        for (int nf = 0; nf < 4; nf++)
            #pragma unroll
            for (int e = 0; e < 4; e++) {
                int row = wm * 16 + (lane >> 2) + ((e >> 1) ? 8 : 0);
                int col = wn * 32 + nf * 8 + (lane & 3) * 2 + (e & 1);
                S[row * 68 + col] = accS[nf][e] * scale;
            }
    }
    __syncthreads();

    for (int i = wid; i < 64; i += 8) {
        float p0 = 0.f, p1 = 0.f;
        if (i < m) {
            float v0 = (lane      < m) ? S[i * 68 + lane]      : -3.4e38f;
            float v1 = (lane + 32 < m) ? S[i * 68 + lane + 32] : -3.4e38f;
            float mx = fmaxf(v0, v1);
            #pragma unroll
            for (int o = 16; o; o >>= 1) mx = fmaxf(mx, __shfl_xor_sync(0xffffffffu, mx, o));
            float e0 = (lane      < m) ? __expf(v0 - mx) : 0.f;
            float e1 = (lane + 32 < m) ? __expf(v1 - mx) : 0.f;
            float sum = e0 + e1;
            #pragma unroll
            for (int o = 16; o; o >>= 1) sum += __shfl_xor_sync(0xffffffffu, sum, o);
            float inv = 1.f / sum;
            p0 = e0 * inv; p1 = e1 * inv;
        }
        uint32_t so = (uint32_t)i * 80 + (uint32_t)((lane >> 3) << 4) + (uint32_t)((lane & 7) << 1);
        *reinterpret_cast<__half*>(smem + AT_P + so)        = __float2half_rn(p0);
        *reinterpret_cast<__half*>(smem + AT_P + 5120 + so) = __float2half_rn(p1);
    }
    __syncthreads();

    {
        float accC[8][4];
        #pragma unroll
        for (int j = 0; j < 8; j++)
            #pragma unroll
            for (int k = 0; k < 4; k++) accC[j][k] = 0.f;

        #pragma unroll
        for (int ch = 0; ch < 2; ch++) {
            #pragma unroll
            for (int ks = 0; ks < 2; ks++) {
                const int kb = ks * 16;
                const uint32_t arow = (uint32_t)(wm * 16 + (lane & 15));
                const uint32_t acol = (uint32_t)((kb + ((lane >> 4) << 3)) * 2);
                const int bl8 = lane & 7, bseg = lane >> 3;
                const uint32_t brow = (uint32_t)(wn * 64 + ((bseg >> 1) << 3) + bl8);
                const uint32_t bcol = (uint32_t)((kb + ((bseg & 1) << 3)) * 2);
                uint32_t a[4], bf[4][4];
                LDSM4(a, sb + AT_P + ch * 5120 + arow * 80 + acol);
                #pragma unroll
                for (int g = 0; g < 4; g++)
                    LDSM4(bf[g], sb + AT_V + ch * 10240 + (brow + g * 16) * 80 + bcol);
                #pragma unroll
                for (int nf = 0; nf < 8; nf++)
                    MMA16816(accC[nf], a, &bf[nf >> 1][(nf & 1) * 2]);
            }
        }
        #pragma unroll
        for (int half = 0; half < 2; half++) {
            int row = wm * 16 + (lane >> 2) + half * 8;
            if (row < m) {
                int gr = off + row;
                #pragma unroll
                for (int nf = 0; nf < 8; nf++) {
                    int col = wn * 64 + nf * 8 + (lane & 3) * 2;
                    __half2 hp = __halves2half2(__float2half_rn(accC[nf][half * 2]),
                                                __float2half_rn(accC[nf][half * 2 + 1]));
                    *reinterpret_cast<uint32_t*>(corrp + pad_addr(gr, col, 4))
                        = reinterpret_cast<uint32_t&>(hp);
                }
            }
        }
    }

    if (tid < ATT) {
        int d = tid;
        float a = 0.f;
        for (int j = 0; j < m; j++) {
            uint32_t so = (uint32_t)(j >> 5) * 10240 + (uint32_t)d * 80
                        + (uint32_t)(((j & 31) >> 3) << 4) + (uint32_t)((j & 7) << 1);
            a += __half2float(*reinterpret_cast<__half*>(smem + AT_V + so));
        }
        a = (a + (float)(MAXA - m) * V0[d]) * 0.02f;
        *reinterpret_cast<__half*>(corrp + pad_addr(Ntot + b, d, 4)) = __float2half_rn(a);
    }
}

// ---------------------------------------------------------------------------
// logits -> cs MLP -> sigmoid -> ragged scatter (K2, Q2 fp16 linear)
// ---------------------------------------------------------------------------
__global__ void final_kernel(const __half* __restrict__ K2, const __half* __restrict__ Q2,
                             const int* __restrict__ offsets, const int* __restrict__ counts,
                             const float* __restrict__ cs1, const float* __restrict__ bcs1,
                             const float* __restrict__ cs2, const float* __restrict__ bcs2,
                             float* __restrict__ out, int Ntot)
{
    __shared__ float q2s[ATT];
    __shared__ float lg[MAXA];
    __shared__ float hs[ATT];

    const int b   = blockIdx.x;
    const int tid = threadIdx.x;
    const int m   = counts[b];
    const int off = offsets[b];
    const float scale = 0.08838834764831845f;

    q2s[tid] = __half2float(Q2[(size_t)b * ATT + tid]);
    __syncthreads();

    const int warp = tid >> 5, lane = tid & 31;
    for (int i = warp; i < MAXA; i += 4) {
        const __half* row = (i < m) ? (K2 + (size_t)(off + i) * ATT)
                                    : (K2 + (size_t)(Ntot + b) * ATT);
        float a = 0.f;
        #pragma unroll
        for (int c = 0; c < 4; c++) {
            int d = lane + c * 32;
            a += __half2float(row[d]) * q2s[d];
        }
        #pragma unroll
        for (int o = 16; o; o >>= 1) a += __shfl_xor_sync(0xffffffffu, a, o);
        if (lane == 0) lg[i] = a * scale;
    }
    __syncthreads();

    {
        float a = bcs1[tid];
        #pragma unroll
        for (int i = 0; i < MAXA; i++) a += lg[i] * cs1[i * ATT + tid];
        hs[tid] = fmaxf(a, 0.f);
    }
    __syncthreads();

    if (tid < MAXA) {
        float a = bcs2[tid];
        #pragma unroll 16
        for (int h = 0; h < ATT; h++) a += hs[h] * cs2[h * MAXA + tid];
        float sel = 1.f / (1.f + __expf(-a));
        if (tid < m) out[off + tid] = sel;
    }
}

// ---------------------------------------------------------------------------
// Host launcher (dual-stream fork/join under graph capture)
// ---------------------------------------------------------------------------
static inline void launch_gemm(cudaStream_t st, bool relu,
                               const char* Ab, const char* Wb,
                               const float* bias, void* Cl, char* Cpad,
                               int M, int K, int N, int ldaChunks, int aBlkChunks)
{
    dim3 grid((M + 127) / 128, N / 128);
    if (relu)
        mma_gemm<true><<<grid, 256, GSMEM, st>>>(Ab, Wb, bias, (uint32_t*)Cl, Cpad,
                                                 M, K, N, ldaChunks, aBlkChunks);
    else
        mma_gemm<false><<<grid, 256, GSMEM, st>>>(Ab, Wb, bias, (uint32_t*)Cl, Cpad,
                                                  M, K, N, ldaChunks, aBlkChunks);
}

extern "C" void kernel_launch(void* const* d_in, const int* in_sizes, int n_in,
                              void* d_out, int out_size)
{
    const float* mol_a  = (const float*)d_in[0];
    const float* node   = (const float*)d_in[1];
    const int*   counts = (const int*)  d_in[2];
    const float* wq1 = (const float*)d_in[3],  *bq1 = (const float*)d_in[4];
    const float* wq2 = (const float*)d_in[5],  *bq2 = (const float*)d_in[6];
    const float* wk1 = (const float*)d_in[7],  *bk1 = (const float*)d_in[8];
    const float* wk2 = (const float*)d_in[9],  *bk2 = (const float*)d_in[10];
    const float* wv1 = (const float*)d_in[11], *bv1 = (const float*)d_in[12];
    const float* wv2 = (const float*)d_in[13], *bv2 = (const float*)d_in[14];
    const float* uk1 = (const float*)d_in[15], *ubk1 = (const float*)d_in[16];
    const float* uk2 = (const float*)d_in[17], *ubk2 = (const float*)d_in[18];
    const float* uq1 = (const float*)d_in[19], *ubq1 = (const float*)d_in[20];
    const float* uq2 = (const float*)d_in[21], *ubq2 = (const float*)d_in[22];
    const float* cs1 = (const float*)d_in[23], *bcs1 = (const float*)d_in[24];
    const float* cs2 = (const float*)d_in[25], *bcs2 = (const float*)d_in[26];
    float* out = (float*)d_out;

    const int N = in_sizes[1] / 512;
    const int B = in_sizes[2];
    const int NPB = N + B;

    char *nodef, *molf, *H, *H2, *corrp, *W;
    __half *KQV, *K2, *Q2;
    float *V0, *b1, *b2;
    int* off;
    cudaGetSymbolAddress((void**)&nodef, g_nodef);
    cudaGetSymbolAddress((void**)&molf,  g_molf);
    cudaGetSymbolAddress((void**)&H,     g_H);
    cudaGetSymbolAddress((void**)&H2,    g_H2);
    cudaGetSymbolAddress((void**)&corrp, g_corrp);
    cudaGetSymbolAddress((void**)&KQV,   g_KQV);
    cudaGetSymbolAddress((void**)&K2,    g_K2);
    cudaGetSymbolAddress((void**)&Q2,    g_Q2);
    cudaGetSymbolAddress((void**)&W,     g_W);
    cudaGetSymbolAddress((void**)&V0,    g_V0);
    cudaGetSymbolAddress((void**)&b1,    g_b1);
    cudaGetSymbolAddress((void**)&b2,    g_b2);
    cudaGetSymbolAddress((void**)&off,   g_off);

    cudaFuncSetAttribute((const void*)mma_gemm<true>,
                         cudaFuncAttributeMaxDynamicSharedMemorySize, GSMEM);
    cudaFuncSetAttribute((const void*)mma_gemm<false>,
                         cudaFuncAttributeMaxDynamicSharedMemorySize, GSMEM);
    cudaFuncSetAttribute(attention_kernel,
                         cudaFuncAttributeMaxDynamicSharedMemorySize, AT_SMEM);

    // chunk-major padded weight arena (byte offsets); W1cat / W2cat contiguous
    const int o_wk1 = 0,        o_wq1 = 327680,   o_wv1 = 655360;   // [768,512]
    const int o_wk2 = 983040,   o_wq2 = 1064960,  o_wv2 = 1146880;  // [384,256]
    const int o_uk1 = 1228800,  o_uk2 = 1310720;
    const int o_uq1 = 1392640,  o_uq2 = 1720320;

    // side stream + events (created per call; not allocations, safe in capture)
    cudaStream_t sB;
    cudaStreamCreateWithFlags(&sB, cudaStreamNonBlocking);
    cudaEvent_t ev0, evW, evB;
    cudaEventCreateWithFlags(&ev0, cudaEventDisableTiming);
    cudaEventCreateWithFlags(&evW, cudaEventDisableTiming);
    cudaEventCreateWithFlags(&evB, cudaEventDisableTiming);

    // fork: stream B joins the capture graph
    cudaEventRecord(ev0, 0);
    cudaStreamWaitEvent(sB, ev0, 0);

    // --- stream B: independent preprocessing ---
    scan_kernel<<<1, 1024, 0, sB>>>(counts, off, B);
    v0_kernel<<<1, ATT, 0, sB>>>(bv1, wv2, bv2, V0);
    {
        int mg = B * 64;
        cvt_pad_kernel<<<(mg + 255) / 256, 256, 0, sB>>>(mol_a, molf, B, 512);
    }

    // --- stream A (default): node convert + weights + biases ---
    {
        int ng = N * 64;
        cvt_pad_kernel<<<(ng + 255) / 256, 256>>>(node, nodef, N, 512);
    }
    {
        WTable t;
        t.s[0] = {wk1, 512, 256, o_wk1}; t.s[1] = {wq1, 512, 256, o_wq1};
        t.s[2] = {wv1, 512, 256, o_wv1}; t.s[3] = {wk2, 256, 128, o_wk2};
        t.s[4] = {wq2, 256, 128, o_wq2}; t.s[5] = {wv2, 256, 128, o_wv2};
        t.s[6] = {uk1, 128, 256, o_uk1}; t.s[7] = {uk2, 256, 128, o_uk2};
        t.s[8] = {uq1, 512, 256, o_uq1}; t.s[9] = {uq2, 256, 128, o_uq2};
        dim3 g(128, 10);
        tsplit_all<<<g, 256>>>(t, W);
    }
    bias_concat<<<5, 256>>>(bk1, bq1, bv1, bk2, bq2, bv2, b1, b2);
    cudaEventRecord(evW, 0);

    // --- stream B: Q2 branch (own H2 arena), overlaps KQV L1 on stream A ---
    cudaStreamWaitEvent(sB, evW, 0);
    launch_gemm(sB, true,  molf, W + o_uq1, ubq1, nullptr, H2, B, 512, 256, 16, 0);
    launch_gemm(sB, false, H2,   W + o_uq2, ubq2, Q2, nullptr, B, 256, 128, 8, 0);
    cudaEventRecord(evB, sB);

    // --- stream A: fused KQV L1 + block-diagonal L2 ---
    launch_gemm(0, true,  nodef, W + o_wk1, b1, nullptr, H, N, 512, 768, 16, 0);
    launch_gemm(0, false, H, W + o_wk2, b2, KQV, nullptr, N, 256, 384, 24, 8);

    // join: attention needs off/V0 (B) and KQV (A); final needs Q2 (B)
    cudaStreamWaitEvent(0, evB, 0);

    attention_kernel<<<B, 256, AT_SMEM>>>(KQV, V0, off, counts, corrp, N);

    launch_gemm(0, true,  corrp, W + o_uk1, ubk1, nullptr, H, NPB, 128, 256, 4, 0);
    launch_gemm(0, false, H,     W + o_uk2, ubk2, K2, nullptr, NPB, 256, 128, 8, 0);

    final_kernel<<<B, 128>>>(K2, Q2, off, counts, cs1, bcs1, cs2, bcs2, out, N);
}